// round 17
// baseline (speedup 1.0000x reference)
#include <cuda_runtime.h>
#include <cstdint>

#define NN 100000
#define EE 1600000
#define IN_DIM 128
#define OUT_DIM 64
#define TT 8
#define EPS_ 1e-7f
#define CSR_CAP (EE + 4 * NN)
#define NB 48                     // nodes per GEMM block (4 warps x 12)
#define COSH1 1.5430806348152437f

typedef unsigned long long ull;

// ---------------- scratch ----------------
__device__ int   g_cnt[NN];
__device__ int   g_off[NN];
__device__ int   g_cur[NN];
__device__ int   g_csr[CSR_CAP];                       // padding slots = NN (dummy)
__device__ float g_hs[(size_t)(NN + 1) * OUT_DIM];     // dinv[n]*(x@W); row NN zeros
__device__ int   g_cursor;

__device__ __forceinline__ void pfma(ull& acc, ull x, ull w) {
    asm("fma.rn.f32x2 %0, %1, %2, %0;" : "+l"(acc) : "l"(x), "l"(w));
}
__device__ __forceinline__ float warp_sum(float v) {
#pragma unroll
    for (int o = 16; o > 0; o >>= 1) v += __shfl_xor_sync(0xffffffffu, v, o);
    return v;
}

// ---------------- kernels ----------------

__global__ void init_kernel() {
    int i = blockIdx.x * blockDim.x + threadIdx.x;
    if (i < NN) g_cnt[i] = 0;
    if (i < OUT_DIM) g_hs[(size_t)NN * OUT_DIM + i] = 0.0f;
    if (i == 0) g_cursor = 0;
}

// 4 edges per thread via int4
__global__ void hist_kernel(const int* __restrict__ dst) {
    int e4 = blockIdx.x * blockDim.x + threadIdx.x;
    if (e4 >= EE / 4) return;
    int4 d = __ldg((const int4*)dst + e4);
    atomicAdd(&g_cnt[d.x], 1);
    atomicAdd(&g_cnt[d.y], 1);
    atomicAdd(&g_cnt[d.z], 1);
    atomicAdd(&g_cnt[d.w], 1);
}

// per-block scan + global bump allocator; pads buckets to multiple of 4
__global__ void offsets_kernel() {
    int i = blockIdx.x * 1024 + threadIdx.x;
    int lane = threadIdx.x & 31, wid = threadIdx.x >> 5;
    int c = (i < NN) ? g_cnt[i] : 0;
    int pc = (c + 3) & ~3;

    int v = pc;
#pragma unroll
    for (int o = 1; o < 32; o <<= 1) {
        int t = __shfl_up_sync(0xffffffffu, v, o);
        if (lane >= o) v += t;
    }
    __shared__ int wsum[32];
    __shared__ int base;
    if (lane == 31) wsum[wid] = v;
    __syncthreads();
    if (wid == 0) {
        int w = wsum[lane];
#pragma unroll
        for (int o = 1; o < 32; o <<= 1) {
            int t = __shfl_up_sync(0xffffffffu, w, o);
            if (lane >= o) w += t;
        }
        wsum[lane] = w;
    }
    __syncthreads();
    int incl = v + ((wid > 0) ? wsum[wid - 1] : 0);
    if (threadIdx.x == 1023) base = atomicAdd(&g_cursor, incl);
    __syncthreads();
    if (i < NN) {
        int off = base + incl - pc;
        g_off[i] = off;
        g_cur[i] = off;
        for (int j = c; j < pc; j++) g_csr[off + j] = NN;   // dummy padding
    }
}

// h_s = dinv * (x @ W): 12 nodes per warp, 4 warps/block (NB=48); dinv inline
__global__ void __launch_bounds__(128) gemm_kernel(const float* __restrict__ x,
                                                   const float* __restrict__ W) {
    extern __shared__ ull sm[];
    ull* Wq = sm;            // [32 kk2][64 j][2] pairs-of-pairs, 32 KB
    ull* xs = sm + 4096;     // [48 node][64 kk], 24 KB

    int tid = threadIdx.x;
    int n0 = blockIdx.x * NB;

    for (int i = tid; i < 64 * 64; i += 128) {
        int kk = i >> 6, j = i & 63;
        int kk2 = kk >> 1, lo = kk & 1;
        float w0 = W[(2 * kk) * OUT_DIM + j];
        float w1 = W[(2 * kk + 1) * OUT_DIM + j];
        ull p; asm("mov.b64 %0, {%1, %2};" : "=l"(p) : "f"(w0), "f"(w1));
        Wq[kk2 * 128 + j * 2 + lo] = p;
    }
    const ull* x2 = (const ull*)x;
    for (int i = tid; i < NB * 64; i += 128) {
        int node = i >> 6, kk = i & 63;
        int gn = n0 + node;
        xs[i] = (gn < NN) ? x2[(size_t)gn * 64 + kk] : 0ull;
    }
    __syncthreads();

    int wid = tid >> 5, lane = tid & 31;
    const ull* xw = xs + wid * 12 * 64;

    ull a0[12], a1[12];
#pragma unroll
    for (int n = 0; n < 12; n++) { a0[n] = 0ull; a1[n] = 0ull; }

#pragma unroll 2
    for (int kk2 = 0; kk2 < 32; kk2++) {
        ulonglong2 wa = *(const ulonglong2*)(Wq + kk2 * 128 + 2 * lane);
        ulonglong2 wb = *(const ulonglong2*)(Wq + kk2 * 128 + 2 * (lane + 32));
#pragma unroll
        for (int n = 0; n < 12; n++) {
            ulonglong2 xv = *(const ulonglong2*)(xw + n * 64 + 2 * kk2);
            pfma(a0[n], xv.x, wa.x);
            pfma(a1[n], xv.x, wb.x);
            pfma(a0[n], xv.y, wa.y);
            pfma(a1[n], xv.y, wb.y);
        }
    }

#pragma unroll
    for (int n = 0; n < 12; n++) {
        int gn = n0 + wid * 12 + n;
        if (gn >= NN) break;
        float lo, hi, lo1, hi1;
        asm("mov.b64 {%0, %1}, %2;" : "=f"(lo), "=f"(hi) : "l"(a0[n]));
        asm("mov.b64 {%0, %1}, %2;" : "=f"(lo1), "=f"(hi1) : "l"(a1[n]));
        float di = rsqrtf((float)(g_cnt[gn] + 1));
        g_hs[(size_t)gn * OUT_DIM + lane]      = (lo + hi) * di;
        g_hs[(size_t)gn * OUT_DIM + lane + 32] = (lo1 + hi1) * di;
    }
}

// 4 edges per thread via int4
__global__ void bucket_kernel(const int* __restrict__ ei) {
    int e4 = blockIdx.x * blockDim.x + threadIdx.x;
    if (e4 >= EE / 4) return;
    int4 s = __ldg((const int4*)ei + e4);
    int4 d = __ldg((const int4*)(ei + EE) + e4);
    int p0 = atomicAdd(&g_cur[d.x], 1); g_csr[p0] = s.x;
    int p1 = atomicAdd(&g_cur[d.y], 1); g_csr[p1] = s.y;
    int p2 = atomicAdd(&g_cur[d.z], 1); g_csr[p2] = s.z;
    int p3 = atomicAdd(&g_cur[d.w], 1); g_csr[p3] = s.w;
}

// fused warp-per-node: gather in-edges then run the 8-step Lorentz recurrence
// entirely in registers (lane holds components 2l, 2l+1). No smem, no barriers.
__global__ void __launch_bounds__(256) fused_kernel(const float* __restrict__ b,
                                                    float* __restrict__ o_out,
                                                    float* __restrict__ z_out) {
    int warp = (blockIdx.x * blockDim.x + threadIdx.x) >> 5;
    int lane = threadIdx.x & 31;
    if (warp >= NN) return;
    const int n = warp;
    const int c0 = 2 * lane;
    const size_t base = (size_t)n * OUT_DIM;

    // ---- gather ----
    int cnt = g_cnt[n];
    int off = g_off[n];
    int mp = (cnt + 3) & ~3;
    const float2* hs2 = (const float2*)g_hs;

    float2 acc = hs2[base / 2 + lane];   // self loop (prescaled by dinv[n])

#pragma unroll 2
    for (int i = 0; i < mp; i += 4) {
        int4 a = __ldg((const int4*)(g_csr + off + i));
        float2 v0 = hs2[(size_t)a.x * 32 + lane];
        float2 v1 = hs2[(size_t)a.y * 32 + lane];
        float2 v2 = hs2[(size_t)a.z * 32 + lane];
        float2 v3 = hs2[(size_t)a.w * 32 + lane];
        acc.x += (v0.x + v1.x) + (v2.x + v3.x);
        acc.y += (v0.y + v1.y) + (v2.y + v3.y);
    }

    float di = rsqrtf((float)(cnt + 1));
    float2 bb = ((const float2*)b)[lane];
    float h0 = fmaf(di, acc.x, bb.x);
    float h1 = fmaf(di, acc.y, bb.y);

    // ---- time loop (warp-per-node, comps 2l / 2l+1 on lane l) ----
    float z0 = (lane == 0) ? 1.0f : 0.0f;   // time coordinate on lane 0
    float z1 = 0.0f;

#pragma unroll
    for (int t = 0; t < TT; t++) {
        float p = z0 * h0 + z1 * h1;
        float p00 = __shfl_sync(0xffffffffu, z0 * h0, 0);
        float lz = warp_sum(p) - 2.0f * p00;

        float u0 = fmaf(lz, z0, h0);
        float u1 = fmaf(lz, z1, h1);

        float q = u0 * u0 + u1 * u1;
        float q00 = __shfl_sync(0xffffffffu, u0 * u0, 0);
        float uu = warp_sum(q) - 2.0f * q00;

        float un2 = fmaxf(uu, EPS_);
        float un = sqrtf(un2);
        float ch, sh_;
        if (un < 0.03f) {                       // series (avoids cancellation)
            ch = fmaf(un2, 0.5f, 1.0f);
            sh_ = fmaf(un2, 0.16666667f, 1.0f);
        } else {
            float e = __expf(un);
            float ei = __fdividef(1.0f, e);
            ch = 0.5f * (e + ei);
            sh_ = __fdividef(0.5f * (e - ei), un);
        }
        z0 = fmaf(ch, z0, sh_ * u0);
        z1 = fmaf(ch, z1, sh_ * u1);

        // spike: arccosh(z0) >= 1  <=>  z0 >= cosh(1)
        float z0b = __shfl_sync(0xffffffffu, z0, 0);
        bool spike = (z0b >= COSH1);
        if (spike) { z0 = (lane == 0) ? 1.0f : 0.0f; z1 = 0.0f; }

        if (lane == 0) {
            float ov = spike ? 1.0f : 0.0f;
            __stcs(o_out + (size_t)t * NN + n, ov);
        }
        float2 zz = make_float2(z0, z1);
        __stcs((float2*)(z_out + (size_t)t * NN * OUT_DIM + base + c0), zz);
    }
}

// ---------------- launch ----------------
extern "C" void kernel_launch(void* const* d_in, const int* in_sizes, int n_in,
                              void* d_out, int out_size) {
    const float* x  = (const float*)d_in[0];
    const int*   ei = (const int*)d_in[1];
    const float* W  = (const float*)d_in[2];
    const float* b  = (const float*)d_in[3];

    float* o_out = (float*)d_out;              // [T, N]
    float* z_out = o_out + (size_t)TT * NN;    // [T, N, 64]

    static cudaStream_t s1 = nullptr;
    static cudaEvent_t evFork = nullptr, evJoin = nullptr;
    if (s1 == nullptr) {
        cudaStreamCreateWithFlags(&s1, cudaStreamNonBlocking);
        cudaEventCreateWithFlags(&evFork, cudaEventDisableTiming);
        cudaEventCreateWithFlags(&evJoin, cudaEventDisableTiming);
        const int GEMM_SMEM = (4096 + NB * 64) * 8;   // 57344 B
        cudaFuncSetAttribute(gemm_kernel, cudaFuncAttributeMaxDynamicSharedMemorySize, GEMM_SMEM);
    }
    const int GEMM_SMEM = (4096 + NB * 64) * 8;

    // s0: init -> hist -> [fork] offsets -> bucket -> [join] fused(gather+time)
    // s1:                        gemm (reads cnt only)
    init_kernel<<<(NN + 255) / 256, 256>>>();
    hist_kernel<<<(EE / 4 + 255) / 256, 256>>>(ei + EE);
    cudaEventRecord(evFork, 0);

    cudaStreamWaitEvent(s1, evFork, 0);
    gemm_kernel<<<(NN + NB - 1) / NB, 128, GEMM_SMEM, s1>>>(x, W);
    cudaEventRecord(evJoin, s1);

    offsets_kernel<<<(NN + 1023) / 1024, 1024>>>();
    bucket_kernel<<<(EE / 4 + 255) / 256, 256>>>(ei);

    cudaStreamWaitEvent(0, evJoin, 0);
    fused_kernel<<<(NN * 32 + 255) / 256, 256>>>(b, o_out, z_out);
}